// round 4
// baseline (speedup 1.0000x reference)
#include <cuda_runtime.h>
#include <math.h>
#include <stdint.h>

// ---------------------------------------------------------------------------
// SD_attn_Cross: Swin-style shifted+dilated windowed cross attention.
// B=4, H=W=128, C=512, HEADS=8, HD=64, window 8x8 dilated 2x2 (total 16x16),
// shift (4,4). 1024 windows of 64 tokens, 8 heads.
//
// Pipeline:
//   1) QV GEMM : x     (65536x512) @ qv_w (512x1024) + qv_b  -> g_qv
//   2) K  GEMM : cross (65536x512) @ k_w  (512x512)  + k_b   -> g_k
//   3) attention: per (window, head) block: gather + RoPE + S=QK^T + band
//      mask + softmax + PV -> g_o (token-major)
//   4) proj GEMM: g_o @ proj_w + proj_b -> out
// ---------------------------------------------------------------------------

#define TOKENS 65536

__device__ float g_qv[(size_t)TOKENS * 1024];   // [t][ head*64+d ] = Q, +512 = V
__device__ float g_k [(size_t)TOKENS * 512];
__device__ float g_o [(size_t)TOKENS * 512];

// ---------------------------------------------------------------------------
// 128x128x16 fp32 SGEMM with bias.  M = gridDim.x*128 rows of A (row-major,
// leading dim K).  B row-major KxN.  All dims divisible by tile sizes here.
// ---------------------------------------------------------------------------
__global__ __launch_bounds__(256, 2)
void sgemm_bias(const float* __restrict__ A, const float* __restrict__ B,
                const float* __restrict__ bias, float* __restrict__ C,
                int K, int N) {
    __shared__ float As[16][132];   // transposed A tile, padded
    __shared__ float Bs[16][128];

    const int bm = blockIdx.x << 7;
    const int bn = blockIdx.y << 7;
    const int tid = threadIdx.x;
    const int ty = tid >> 4;
    const int tx = tid & 15;

    float acc[8][8];
#pragma unroll
    for (int i = 0; i < 8; ++i)
#pragma unroll
        for (int j = 0; j < 8; ++j) acc[i][j] = 0.0f;

    const float* Ab = A + (size_t)bm * K;
    const float* Bb = B + bn;

    for (int k0 = 0; k0 < K; k0 += 16) {
        // load A tile 128x16 (2 float4 per thread), store transposed
#pragma unroll
        for (int l = 0; l < 2; ++l) {
            int idx = tid + (l << 8);
            int row = idx >> 2;
            int c4  = (idx & 3) << 2;
            float4 v = *(const float4*)(Ab + (size_t)row * K + k0 + c4);
            As[c4 + 0][row] = v.x;
            As[c4 + 1][row] = v.y;
            As[c4 + 2][row] = v.z;
            As[c4 + 3][row] = v.w;
        }
        // load B tile 16x128 (2 float4 per thread)
#pragma unroll
        for (int l = 0; l < 2; ++l) {
            int idx = tid + (l << 8);
            int row = idx >> 5;
            int c4  = (idx & 31) << 2;
            *(float4*)(&Bs[row][c4]) = *(const float4*)(Bb + (size_t)(k0 + row) * N + c4);
        }
        __syncthreads();

#pragma unroll
        for (int kk = 0; kk < 16; ++kk) {
            float a[8], b[8];
            *(float4*)(a)     = *(const float4*)(&As[kk][ty * 8]);
            *(float4*)(a + 4) = *(const float4*)(&As[kk][ty * 8 + 4]);
            *(float4*)(b)     = *(const float4*)(&Bs[kk][tx * 8]);
            *(float4*)(b + 4) = *(const float4*)(&Bs[kk][tx * 8 + 4]);
#pragma unroll
            for (int i = 0; i < 8; ++i)
#pragma unroll
                for (int j = 0; j < 8; ++j)
                    acc[i][j] = fmaf(a[i], b[j], acc[i][j]);
        }
        __syncthreads();
    }

#pragma unroll
    for (int i = 0; i < 8; ++i) {
        size_t row = (size_t)(bm + ty * 8 + i);
#pragma unroll
        for (int j = 0; j < 8; j += 4) {
            int col = bn + tx * 8 + j;
            float4 o;
            o.x = acc[i][j + 0] + bias[col + 0];
            o.y = acc[i][j + 1] + bias[col + 1];
            o.z = acc[i][j + 2] + bias[col + 2];
            o.w = acc[i][j + 3] + bias[col + 3];
            *(float4*)(C + row * N + col) = o;
        }
    }
}

// ---------------------------------------------------------------------------
// Attention: one block (256 threads) per (window w in [0,1024), head in [0,8)).
// ---------------------------------------------------------------------------
__global__ __launch_bounds__(256)
void attn_kernel() {
    const int blk = blockIdx.x;
    const int hh  = blk & 7;
    const int w   = blk >> 3;          // window index in [0, 1024)
    const int b   = w >> 8;            // batch
    const int rem = w & 255;
    const int wij = rem >> 2;          // wi*8 + wj
    const int d   = rem & 3;           // dilation index
    const int wi  = wij >> 3;
    const int wj  = wij & 7;

    __shared__ float bufA[64][66];     // Q, later V  [token][hd]
    __shared__ float bufB[64][66];     // K^T, later P [hd][token] / [token][token]
    __shared__ int   st[64];           // token -> flat token index
    __shared__ int   sband[64];        // token -> row band id

    const int tid = threadIdx.x;

    if (tid < 64) {
        int n = tid;
        int gi = wi * 16 + ((n >> 3) << 1) + (d >> 1);   // grid row
        int gj = wj * 16 + ((n & 7) << 1) + (d & 1);     // grid col
        int h  = (gi + 4) & 127;
        int wc = (gj + 4) & 127;
        st[n] = (b << 14) | (h << 7) | wc;               // b*16384 + h*128 + wc
        sband[n] = (gi < 120) ? 0 : ((gi < 124) ? 1 : 2);
    }
    __syncthreads();

    // ---- load Q (bufA) and K^T (bufB) with RoPE ----
    const int row  = tid >> 2;         // token in [0,64)
    const int quad = tid & 3;          // 16-col chunk
    const int t    = st[row];
    const float* qg = g_qv + (size_t)t * 1024 + hh * 64 + quad * 16;
    const float* kg = g_k  + (size_t)t * 512  + hh * 64 + quad * 16;
    const float fh = (float)(row >> 3);
    const float fw = (float)(row & 7);
    const float L  = 13.287712379549449f / 16.0f;   // log2(10000)/16

#pragma unroll
    for (int f = 0; f < 4; ++f) {
        const int c0 = quad * 16 + f * 4;
        float4 q4 = *(const float4*)(qg + f * 4);
        float4 k4 = *(const float4*)(kg + f * 4);
        float rq[4] = {q4.x, q4.y, q4.z, q4.w};
        float rk[4] = {k4.x, k4.y, k4.z, k4.w};
#pragma unroll
        for (int e = 0; e < 2; ++e) {
            int p = (c0 >> 1) + e;                 // rotation pair index [0,32)
            float coord = (p < 16) ? fh : fw;
            float inv = exp2f(-(float)(p & 15) * L);
            float ang = coord * inv;
            float sv, cv;
            sincosf(ang, &sv, &cv);
            float x1 = rq[2 * e], x2 = rq[2 * e + 1];
            rq[2 * e]     = x1 * cv - x2 * sv;
            rq[2 * e + 1] = x1 * sv + x2 * cv;
            x1 = rk[2 * e]; x2 = rk[2 * e + 1];
            rk[2 * e]     = x1 * cv - x2 * sv;
            rk[2 * e + 1] = x1 * sv + x2 * cv;
        }
#pragma unroll
        for (int e2 = 0; e2 < 4; ++e2) {
            bufA[row][c0 + e2] = rq[e2];
            bufB[c0 + e2][row] = rk[e2];           // transposed store
        }
    }
    __syncthreads();

    // ---- S = scale * Q K^T  (4x4 per thread) ----
    const int ty = tid >> 4;
    const int tx = tid & 15;
    float S[4][4];
#pragma unroll
    for (int i = 0; i < 4; ++i)
#pragma unroll
        for (int j = 0; j < 4; ++j) S[i][j] = 0.0f;

#pragma unroll 8
    for (int kk = 0; kk < 64; ++kk) {
        float a[4], bb[4];
#pragma unroll
        for (int i = 0; i < 4; ++i) a[i]  = bufA[ty * 4 + i][kk];
#pragma unroll
        for (int j = 0; j < 4; ++j) bb[j] = bufB[kk][tx * 4 + j];
#pragma unroll
        for (int i = 0; i < 4; ++i)
#pragma unroll
            for (int j = 0; j < 4; ++j)
                S[i][j] = fmaf(a[i], bb[j], S[i][j]);
    }

    // ---- mask + softmax (rows ty*4..+3, segment across 16 tx lanes) ----
    const float scale = 0.125f;   // 64^-0.5
    int bandr[4], bandc[4];
#pragma unroll
    for (int i = 0; i < 4; ++i) bandr[i] = sband[ty * 4 + i];
#pragma unroll
    for (int j = 0; j < 4; ++j) bandc[j] = sband[tx * 4 + j];

#pragma unroll
    for (int i = 0; i < 4; ++i)
#pragma unroll
        for (int j = 0; j < 4; ++j)
            S[i][j] = S[i][j] * scale + ((bandr[i] == bandc[j]) ? 0.0f : -1e9f);

#pragma unroll
    for (int i = 0; i < 4; ++i) {
        float m = fmaxf(fmaxf(S[i][0], S[i][1]), fmaxf(S[i][2], S[i][3]));
#pragma unroll
        for (int off = 1; off < 16; off <<= 1)
            m = fmaxf(m, __shfl_xor_sync(0xffffffffu, m, off));
        float s = 0.0f;
#pragma unroll
        for (int j = 0; j < 4; ++j) {
            S[i][j] = expf(S[i][j] - m);
            s += S[i][j];
        }
#pragma unroll
        for (int off = 1; off < 16; off <<= 1)
            s += __shfl_xor_sync(0xffffffffu, s, off);
        float r = 1.0f / s;
#pragma unroll
        for (int j = 0; j < 4; ++j) S[i][j] *= r;
    }

    __syncthreads();   // everyone done reading bufA/bufB

    // ---- store P into bufB, load V into bufA ----
#pragma unroll
    for (int i = 0; i < 4; ++i)
#pragma unroll
        for (int j = 0; j < 4; ++j)
            bufB[ty * 4 + i][tx * 4 + j] = S[i][j];

    const float* vg = g_qv + (size_t)t * 1024 + 512 + hh * 64 + quad * 16;
#pragma unroll
    for (int f = 0; f < 4; ++f) {
        float4 v4 = *(const float4*)(vg + f * 4);
        int c0 = quad * 16 + f * 4;
        bufA[row][c0 + 0] = v4.x;
        bufA[row][c0 + 1] = v4.y;
        bufA[row][c0 + 2] = v4.z;
        bufA[row][c0 + 3] = v4.w;
    }
    __syncthreads();

    // ---- O = P V  (4x4 per thread) ----
    float O[4][4];
#pragma unroll
    for (int i = 0; i < 4; ++i)
#pragma unroll
        for (int j = 0; j < 4; ++j) O[i][j] = 0.0f;

#pragma unroll 8
    for (int kk = 0; kk < 64; ++kk) {
        float a[4], bb[4];
#pragma unroll
        for (int i = 0; i < 4; ++i) a[i]  = bufB[ty * 4 + i][kk];
#pragma unroll
        for (int j = 0; j < 4; ++j) bb[j] = bufA[kk][tx * 4 + j];
#pragma unroll
        for (int i = 0; i < 4; ++i)
#pragma unroll
            for (int j = 0; j < 4; ++j)
                O[i][j] = fmaf(a[i], bb[j], O[i][j]);
    }

    // ---- scatter O to token-major g_o ----
#pragma unroll
    for (int i = 0; i < 4; ++i) {
        int tr = st[ty * 4 + i];
        float4 o4;
        o4.x = O[i][0]; o4.y = O[i][1]; o4.z = O[i][2]; o4.w = O[i][3];
        *(float4*)(g_o + (size_t)tr * 512 + hh * 64 + tx * 4) = o4;
    }
}

// ---------------------------------------------------------------------------
extern "C" void kernel_launch(void* const* d_in, const int* in_sizes, int n_in,
                              void* d_out, int out_size) {
    (void)in_sizes; (void)n_in; (void)out_size;
    const float* x      = (const float*)d_in[0];
    const float* cross  = (const float*)d_in[1];
    const float* qv_w   = (const float*)d_in[2];
    const float* qv_b   = (const float*)d_in[3];
    const float* k_w    = (const float*)d_in[4];
    const float* k_b    = (const float*)d_in[5];
    const float* proj_w = (const float*)d_in[6];
    const float* proj_b = (const float*)d_in[7];
    float* out = (float*)d_out;

    float *qv_ptr = nullptr, *k_ptr = nullptr, *o_ptr = nullptr;
    cudaGetSymbolAddress((void**)&qv_ptr, g_qv);
    cudaGetSymbolAddress((void**)&k_ptr,  g_k);
    cudaGetSymbolAddress((void**)&o_ptr,  g_o);

    // 1) QV = x @ qv_w + qv_b        (65536 x 1024)
    sgemm_bias<<<dim3(512, 8), 256>>>(x, qv_w, qv_b, qv_ptr, 512, 1024);
    // 2) K  = cross @ k_w + k_b      (65536 x 512)
    sgemm_bias<<<dim3(512, 4), 256>>>(cross, k_w, k_b, k_ptr, 512, 512);
    // 3) windowed attention -> g_o
    attn_kernel<<<8192, 256>>>();
    // 4) out = g_o @ proj_w + proj_b (65536 x 512)
    sgemm_bias<<<dim3(512, 4), 256>>>(o_ptr, proj_w, proj_b, out, 512, 512);
}

// round 8
// speedup vs baseline: 2.5458x; 2.5458x over previous
#include <cuda_runtime.h>
#include <math.h>
#include <stdint.h>

// ---------------------------------------------------------------------------
// SD_attn_Cross on GB300 (compute_103 PTX => no tcgen05; use mma.sync tf32).
//   1) QV = x @ qv_w + qv_b          (tf32 mma.sync)
//   2) K  = cross @ k_w + k_b        (tf32 mma.sync)
//   3) windowed attention (fp32 SIMT)
//   4) out = g_o @ proj_w + proj_b   (tf32 mma.sync)
// ---------------------------------------------------------------------------

#define TOKENS 65536

__device__ float g_qv[(size_t)TOKENS * 1024];
__device__ float g_k [(size_t)TOKENS * 512];
__device__ float g_o [(size_t)TOKENS * 512];

// ------------------------------ PTX helpers --------------------------------
__device__ __forceinline__ uint32_t smem_u32(const void* p) {
    uint32_t a;
    asm("{ .reg .u64 t; cvta.to.shared.u64 t, %1; cvt.u32.u64 %0, t; }"
        : "=r"(a) : "l"(p));
    return a;
}
#define CP_ASYNC16(sdst, gsrc) \
    asm volatile("cp.async.cg.shared.global [%0], [%1], 16;" :: "r"(sdst), "l"(gsrc) : "memory")
#define CP_COMMIT() asm volatile("cp.async.commit_group;" ::: "memory")

__device__ __forceinline__ uint32_t f2tf32(float x) {
    uint32_t u;
    asm("cvt.rna.tf32.f32 %0, %1;" : "=r"(u) : "f"(x));
    return u;
}
__device__ __forceinline__ void mma_tf32(float c[4], const uint32_t a[4],
                                         const uint32_t b[2]) {
    asm volatile(
        "mma.sync.aligned.m16n8k8.row.col.f32.tf32.tf32.f32 "
        "{%0,%1,%2,%3}, {%4,%5,%6,%7}, {%8,%9}, {%0,%1,%2,%3};"
        : "+f"(c[0]), "+f"(c[1]), "+f"(c[2]), "+f"(c[3])
        : "r"(a[0]), "r"(a[1]), "r"(a[2]), "r"(a[3]), "r"(b[0]), "r"(b[1]));
}

// ------------------------- tf32 tensor-core GEMM ---------------------------
// C[m,n] = sum_k A[m,k] * B[k,n] + bias[n].   K = 512 fixed, M,N mult of 128.
// Block tile 128x128, 256 threads = 8 warps (2m x 4n), warp tile 64x32.
// BK=16, 2-stage cp.async double buffer.
#define MM_BK 16

__global__ __launch_bounds__(256, 2)
void mm_tf32(const float* __restrict__ A, const float* __restrict__ B,
             const float* __restrict__ bias, float* __restrict__ C, int Ntot) {
    __shared__ float As[2][128][20];   // [stage][m][k], stride 20 => bank-clean
    __shared__ float Bs[2][MM_BK][128];

    const int tid  = threadIdx.x;
    const int wid  = tid >> 5;
    const int lane = tid & 31;
    const int g    = lane >> 2;        // group id (0..7)
    const int t    = lane & 3;         // thread-in-group (0..3)
    const int wm   = wid & 1;          // warp m (0..1)  -> 64 rows
    const int wn   = wid >> 1;         // warp n (0..3)  -> 32 cols
    const int n0   = blockIdx.x << 7;
    const int m0   = blockIdx.y << 7;

    // cp.async source/dest mapping
    const int arow = tid >> 2;         // +64*l
    const int ak4  = (tid & 3) << 2;
    const int brow = tid >> 5;         // +8*l
    const int bc4  = (tid & 31) << 2;

    const float* gA = A + (size_t)(m0 + arow) * 512 + ak4;
    const float* gB = B + (size_t)brow * Ntot + n0 + bc4;

    float acc[2][4][4];                // [mt pair? no: mt in 0..3 packed]
    float acc2[2][4][4];
    // acc layout: acc[mt<2][nt][4], acc2[mt-2][nt][4]
#pragma unroll
    for (int i = 0; i < 2; ++i)
#pragma unroll
        for (int j = 0; j < 4; ++j)
#pragma unroll
            for (int e = 0; e < 4; ++e) { acc[i][j][e] = 0.f; acc2[i][j][e] = 0.f; }

    // ---- prologue: stage 0 ----
    {
#pragma unroll
        for (int l = 0; l < 2; ++l) {
            CP_ASYNC16(smem_u32(&As[0][arow + 64 * l][ak4]), gA + (size_t)(64 * l) * 512);
            CP_ASYNC16(smem_u32(&Bs[0][brow + 8 * l][bc4]),  gB + (size_t)(8 * l) * Ntot);
        }
        CP_COMMIT();
    }

    const int NCH = 512 / MM_BK;       // 32 chunks
    for (int c = 0; c < NCH; ++c) {
        const int cur = c & 1;
        if (c + 1 < NCH) {
            const int nxt = (c + 1) & 1;
            const float* pA = gA + (c + 1) * MM_BK;
            const float* pB = gB + (size_t)(c + 1) * MM_BK * Ntot;
#pragma unroll
            for (int l = 0; l < 2; ++l) {
                CP_ASYNC16(smem_u32(&As[nxt][arow + 64 * l][ak4]), pA + (size_t)(64 * l) * 512);
                CP_ASYNC16(smem_u32(&Bs[nxt][brow + 8 * l][bc4]),  pB + (size_t)(8 * l) * Ntot);
            }
            CP_COMMIT();
            asm volatile("cp.async.wait_group 1;" ::: "memory");
        } else {
            asm volatile("cp.async.wait_group 0;" ::: "memory");
        }
        __syncthreads();

#pragma unroll
        for (int kk = 0; kk < MM_BK; kk += 8) {
            uint32_t af[4][4];         // [mt][frag]
            uint32_t bf[4][2];         // [nt][frag]
#pragma unroll
            for (int mt = 0; mt < 4; ++mt) {
                const int mr = wm * 64 + mt * 16;
                af[mt][0] = f2tf32(As[cur][mr + g][kk + t]);
                af[mt][1] = f2tf32(As[cur][mr + g + 8][kk + t]);
                af[mt][2] = f2tf32(As[cur][mr + g][kk + t + 4]);
                af[mt][3] = f2tf32(As[cur][mr + g + 8][kk + t + 4]);
            }
#pragma unroll
            for (int nt = 0; nt < 4; ++nt) {
                const int nc = wn * 32 + nt * 8 + g;
                bf[nt][0] = f2tf32(Bs[cur][kk + t][nc]);
                bf[nt][1] = f2tf32(Bs[cur][kk + t + 4][nc]);
            }
#pragma unroll
            for (int mt = 0; mt < 2; ++mt)
#pragma unroll
                for (int nt = 0; nt < 4; ++nt)
                    mma_tf32(acc[mt][nt], af[mt], bf[nt]);
#pragma unroll
            for (int mt = 0; mt < 2; ++mt)
#pragma unroll
                for (int nt = 0; nt < 4; ++nt)
                    mma_tf32(acc2[mt][nt], af[mt + 2], bf[nt]);
        }
        __syncthreads();
    }

    // ---- epilogue: c0:(g, 2t) c1:(g, 2t+1) c2:(g+8, 2t) c3:(g+8, 2t+1) ----
    float2 bv[4];
#pragma unroll
    for (int nt = 0; nt < 4; ++nt) {
        const int col = n0 + wn * 32 + nt * 8 + 2 * t;
        bv[nt].x = bias[col];
        bv[nt].y = bias[col + 1];
    }
#pragma unroll
    for (int mt = 0; mt < 4; ++mt) {
        const int mr = m0 + wm * 64 + mt * 16;
        float (*ac)[4] = (mt < 2) ? acc[mt] : acc2[mt - 2];
#pragma unroll
        for (int nt = 0; nt < 4; ++nt) {
            const int col = n0 + wn * 32 + nt * 8 + 2 * t;
            float2 o0, o1;
            o0.x = ac[nt][0] + bv[nt].x;
            o0.y = ac[nt][1] + bv[nt].y;
            o1.x = ac[nt][2] + bv[nt].x;
            o1.y = ac[nt][3] + bv[nt].y;
            *(float2*)(C + (size_t)(mr + g) * Ntot + col)     = o0;
            *(float2*)(C + (size_t)(mr + g + 8) * Ntot + col) = o1;
        }
    }
}

// ---------------------------------------------------------------------------
// Attention: one block (256 threads) per (window w in [0,1024), head in [0,8)).
// ---------------------------------------------------------------------------
__global__ __launch_bounds__(256)
void attn_kernel() {
    const int blk = blockIdx.x;
    const int hh  = blk & 7;
    const int w   = blk >> 3;
    const int b   = w >> 8;
    const int rem = w & 255;
    const int wij = rem >> 2;
    const int d   = rem & 3;
    const int wi  = wij >> 3;
    const int wj  = wij & 7;

    __shared__ float bufA[64][66];
    __shared__ float bufB[64][66];
    __shared__ int   st[64];
    __shared__ int   sband[64];

    const int tid = threadIdx.x;

    if (tid < 64) {
        int n = tid;
        int gi = wi * 16 + ((n >> 3) << 1) + (d >> 1);
        int gj = wj * 16 + ((n & 7) << 1) + (d & 1);
        int h  = (gi + 4) & 127;
        int wc = (gj + 4) & 127;
        st[n] = (b << 14) | (h << 7) | wc;
        sband[n] = (gi < 120) ? 0 : ((gi < 124) ? 1 : 2);
    }
    __syncthreads();

    const int row  = tid >> 2;
    const int quad = tid & 3;
    const int t    = st[row];
    const float* qg = g_qv + (size_t)t * 1024 + hh * 64 + quad * 16;
    const float* kg = g_k  + (size_t)t * 512  + hh * 64 + quad * 16;
    const float fh = (float)(row >> 3);
    const float fw = (float)(row & 7);
    const float L  = 13.287712379549449f / 16.0f;

#pragma unroll
    for (int f = 0; f < 4; ++f) {
        const int c0 = quad * 16 + f * 4;
        float4 q4 = *(const float4*)(qg + f * 4);
        float4 k4 = *(const float4*)(kg + f * 4);
        float rq[4] = {q4.x, q4.y, q4.z, q4.w};
        float rk[4] = {k4.x, k4.y, k4.z, k4.w};
#pragma unroll
        for (int e = 0; e < 2; ++e) {
            int p = (c0 >> 1) + e;
            float coord = (p < 16) ? fh : fw;
            float inv = exp2f(-(float)(p & 15) * L);
            float ang = coord * inv;
            float sv, cv;
            sincosf(ang, &sv, &cv);
            float x1 = rq[2 * e], x2 = rq[2 * e + 1];
            rq[2 * e]     = x1 * cv - x2 * sv;
            rq[2 * e + 1] = x1 * sv + x2 * cv;
            x1 = rk[2 * e]; x2 = rk[2 * e + 1];
            rk[2 * e]     = x1 * cv - x2 * sv;
            rk[2 * e + 1] = x1 * sv + x2 * cv;
        }
#pragma unroll
        for (int e2 = 0; e2 < 4; ++e2) {
            bufA[row][c0 + e2] = rq[e2];
            bufB[c0 + e2][row] = rk[e2];
        }
    }
    __syncthreads();

    const int ty = tid >> 4;
    const int tx = tid & 15;
    float S[4][4];
#pragma unroll
    for (int i = 0; i < 4; ++i)
#pragma unroll
        for (int j = 0; j < 4; ++j) S[i][j] = 0.0f;

#pragma unroll 8
    for (int kk = 0; kk < 64; ++kk) {
        float a[4], bb[4];
#pragma unroll
        for (int i = 0; i < 4; ++i) a[i]  = bufA[ty * 4 + i][kk];
#pragma unroll
        for (int j = 0; j < 4; ++j) bb[j] = bufB[kk][tx * 4 + j];
#pragma unroll
        for (int i = 0; i < 4; ++i)
#pragma unroll
            for (int j = 0; j < 4; ++j)
                S[i][j] = fmaf(a[i], bb[j], S[i][j]);
    }

    const float scale = 0.125f;
    int bandr[4], bandc[4];
#pragma unroll
    for (int i = 0; i < 4; ++i) bandr[i] = sband[ty * 4 + i];
#pragma unroll
    for (int j = 0; j < 4; ++j) bandc[j] = sband[tx * 4 + j];

#pragma unroll
    for (int i = 0; i < 4; ++i)
#pragma unroll
        for (int j = 0; j < 4; ++j)
            S[i][j] = S[i][j] * scale + ((bandr[i] == bandc[j]) ? 0.0f : -1e9f);

#pragma unroll
    for (int i = 0; i < 4; ++i) {
        float m = fmaxf(fmaxf(S[i][0], S[i][1]), fmaxf(S[i][2], S[i][3]));
#pragma unroll
        for (int off = 1; off < 16; off <<= 1)
            m = fmaxf(m, __shfl_xor_sync(0xffffffffu, m, off));
        float s = 0.0f;
#pragma unroll
        for (int j = 0; j < 4; ++j) {
            S[i][j] = expf(S[i][j] - m);
            s += S[i][j];
        }
#pragma unroll
        for (int off = 1; off < 16; off <<= 1)
            s += __shfl_xor_sync(0xffffffffu, s, off);
        float r = 1.0f / s;
#pragma unroll
        for (int j = 0; j < 4; ++j) S[i][j] *= r;
    }

    __syncthreads();

#pragma unroll
    for (int i = 0; i < 4; ++i)
#pragma unroll
        for (int j = 0; j < 4; ++j)
            bufB[ty * 4 + i][tx * 4 + j] = S[i][j];

    const float* vg = g_qv + (size_t)t * 1024 + 512 + hh * 64 + quad * 16;
#pragma unroll
    for (int f = 0; f < 4; ++f) {
        float4 v4 = *(const float4*)(vg + f * 4);
        int c0 = quad * 16 + f * 4;
        bufA[row][c0 + 0] = v4.x;
        bufA[row][c0 + 1] = v4.y;
        bufA[row][c0 + 2] = v4.z;
        bufA[row][c0 + 3] = v4.w;
    }
    __syncthreads();

    float O[4][4];
#pragma unroll
    for (int i = 0; i < 4; ++i)
#pragma unroll
        for (int j = 0; j < 4; ++j) O[i][j] = 0.0f;

#pragma unroll 8
    for (int kk = 0; kk < 64; ++kk) {
        float a[4], bb[4];
#pragma unroll
        for (int i = 0; i < 4; ++i) a[i]  = bufB[ty * 4 + i][kk];
#pragma unroll
        for (int j = 0; j < 4; ++j) bb[j] = bufA[kk][tx * 4 + j];
#pragma unroll
        for (int i = 0; i < 4; ++i)
#pragma unroll
            for (int j = 0; j < 4; ++j)
                O[i][j] = fmaf(a[i], bb[j], O[i][j]);
    }

#pragma unroll
    for (int i = 0; i < 4; ++i) {
        int tr = st[ty * 4 + i];
        float4 o4;
        o4.x = O[i][0]; o4.y = O[i][1]; o4.z = O[i][2]; o4.w = O[i][3];
        *(float4*)(g_o + (size_t)tr * 512 + hh * 64 + tx * 4) = o4;
    }
}

// ---------------------------------------------------------------------------
extern "C" void kernel_launch(void* const* d_in, const int* in_sizes, int n_in,
                              void* d_out, int out_size) {
    (void)in_sizes; (void)n_in; (void)out_size;
    const float* x      = (const float*)d_in[0];
    const float* cross  = (const float*)d_in[1];
    const float* qv_w   = (const float*)d_in[2];
    const float* qv_b   = (const float*)d_in[3];
    const float* k_w    = (const float*)d_in[4];
    const float* k_b    = (const float*)d_in[5];
    const float* proj_w = (const float*)d_in[6];
    const float* proj_b = (const float*)d_in[7];
    float* out = (float*)d_out;

    float *qv_ptr = nullptr, *k_ptr = nullptr, *o_ptr = nullptr;
    cudaGetSymbolAddress((void**)&qv_ptr, g_qv);
    cudaGetSymbolAddress((void**)&k_ptr,  g_k);
    cudaGetSymbolAddress((void**)&o_ptr,  g_o);

    // 1) QV = x @ qv_w + qv_b        (65536 x 1024)
    mm_tf32<<<dim3(8, 512), 256>>>(x, qv_w, qv_b, qv_ptr, 1024);
    // 2) K  = cross @ k_w + k_b      (65536 x 512)
    mm_tf32<<<dim3(4, 512), 256>>>(cross, k_w, k_b, k_ptr, 512);
    // 3) windowed attention -> g_o
    attn_kernel<<<8192, 256>>>();
    // 4) out = g_o @ proj_w + proj_b (65536 x 512)
    mm_tf32<<<dim3(4, 512), 256>>>(o_ptr, proj_w, proj_b, out, 512);
}